// round 7
// baseline (speedup 1.0000x reference)
#include <cuda_runtime.h>
#include <cuda_fp16.h>
#include <cstdint>

// RBFN fused warp-specialized kernel.
// E-warps (4-7): GEMM1 fp16 mma + phi epilogue.  G-warps (0-3): GEMM2 fp16 mma.
// out[8192,64] = sqrt(1 + max(x2 + c2 - 2*X@C^T, 0)) @ W

#define D_TOT   8192
#define N_TOT   8192
#define KD      128
#define LD      64
#define BD      128
#define BN      128
#define NSPLIT  2
#define CHUNKS  (N_TOT / BN / NSPLIT)   // 32
#define THREADS 256

// shared memory layout (32-bit word offsets)
#define XH_O 0                    // X tile  [128][68] half2 words
#define CH_O 8704                 // C chunk [2][128][68]
#define PH_O 26112                // phi     [2][128][68]
#define WS_O 43520                // W^T     [2][64][68]
#define X2_O 52224                // [128]
#define C2_O 52352                // [2][128]
#define SM_WORDS 52608
#define SMEM_BYTES (SM_WORDS * 4)

#define CH_BUF 8704
#define PH_BUF 8704
#define WS_BUF 4352

__device__ float  x2_g[D_TOT];
__device__ float  c2_g[N_TOT];
__device__ __half xh_g[D_TOT * KD];    // fp16-rn xs
__device__ __half ch_g[N_TOT * KD];    // fp16-rn centre
__device__ __half wt_g[LD * N_TOT];    // fp16-rn weight, TRANSPOSED [l][n]

// ------------------------- helpers -------------------------
__device__ __forceinline__ uint32_t smem_u32(const void* p) {
    uint32_t a;
    asm("{ .reg .u64 t; cvta.to.shared.u64 t, %1; cvt.u32.u64 %0, t; }" : "=r"(a) : "l"(p));
    return a;
}
__device__ __forceinline__ float fsqrt_ap(float x) {
    float r; asm("sqrt.approx.f32 %0, %1;" : "=f"(r) : "f"(x)); return r;
}
__device__ __forceinline__ void cp16(uint32_t dst, const void* src) {
    asm volatile("cp.async.ca.shared.global [%0], [%1], 16;" :: "r"(dst), "l"(src) : "memory");
}
__device__ __forceinline__ void cpcommit() {
    asm volatile("cp.async.commit_group;" ::: "memory");
}
template <int N>
__device__ __forceinline__ void cpwait() {
    asm volatile("cp.async.wait_group %0;" :: "n"(N) : "memory");
}
__device__ __forceinline__ void barsync(int id, int cnt) {
    asm volatile("bar.sync %0, %1;" :: "r"(id), "r"(cnt) : "memory");
}
__device__ __forceinline__ void mma_f16(float* d, const uint32_t* a, const uint32_t* b) {
    asm volatile("mma.sync.aligned.m16n8k16.row.col.f32.f16.f16.f32 "
                 "{%0,%1,%2,%3}, {%4,%5,%6,%7}, {%8,%9}, {%0,%1,%2,%3};"
                 : "+f"(d[0]), "+f"(d[1]), "+f"(d[2]), "+f"(d[3])
                 : "r"(a[0]), "r"(a[1]), "r"(a[2]), "r"(a[3]),
                   "r"(b[0]), "r"(b[1]));
}

// ---------------------------------------------------------------------------
// Fused prologue: blocks [0,2048) = norms + fp16 rows; blocks [2048,2176) =
// weight transpose tiles (smem, coalesced both sides).
// ---------------------------------------------------------------------------
__global__ void prologue_kernel(const float* __restrict__ xs,
                                const float* __restrict__ centre,
                                const float* __restrict__ weight) {
    __shared__ float ts[64 * 65];
    if (blockIdx.x < 2048) {
        int gw   = (blockIdx.x * blockDim.x + threadIdx.x) >> 5;
        int lane = threadIdx.x & 31;
        const float* src; float* dst; __half* dsth; int row;
        if (gw < D_TOT) { src = xs;     dst = x2_g; dsth = xh_g; row = gw; }
        else            { src = centre; dst = c2_g; dsth = ch_g; row = gw - D_TOT; }
        float4 v = ((const float4*)(src + (size_t)row * KD))[lane];

        __half2 h01 = __float22half2_rn(make_float2(v.x, v.y));
        __half2 h23 = __float22half2_rn(make_float2(v.z, v.w));
        uint2 u = make_uint2(*(uint32_t*)&h01, *(uint32_t*)&h23);
        *(uint2*)(dsth + (size_t)row * KD + 4 * lane) = u;

        float s = v.x * v.x + v.y * v.y + v.z * v.z + v.w * v.w;
        #pragma unroll
        for (int off = 16; off; off >>= 1) s += __shfl_xor_sync(0xffffffffu, s, off);
        if (lane == 0) dst[row] = s;
    } else {
        int nb = (blockIdx.x - 2048) * 64;
        int tid = threadIdx.x;
        #pragma unroll
        for (int it = 0; it < 16; ++it) {
            int idx = it * THREADS + tid;
            int n_loc = idx >> 6, l = idx & 63;
            ts[n_loc * 65 + l] = weight[(size_t)(nb + n_loc) * LD + l];
        }
        __syncthreads();
        #pragma unroll
        for (int it = 0; it < 16; ++it) {
            int idx = it * THREADS + tid;
            int l = idx >> 6, n_loc = idx & 63;
            wt_g[(size_t)l * N_TOT + nb + n_loc] = __float2half_rn(ts[n_loc * 65 + l]);
        }
    }
}

// ---------------------------------------------------------------------------
// Main kernel. 128 CTAs: d-tile = bid & 63, N-split = bid >> 6.
// ---------------------------------------------------------------------------
__global__ __launch_bounds__(THREADS, 1)
void rbfn_main_kernel(float* __restrict__ out) {
    extern __shared__ float smf[];
    uint32_t* su = (uint32_t*)smf;
    const uint32_t sb = smem_u32(smf);

    const int tid = threadIdx.x;
    const int wid = tid >> 5, lid = tid & 31;
    const int gid = lid >> 2, ctg = lid & 3;

    const int db    = (blockIdx.x & 63) * BD;
    const int split = blockIdx.x >> 6;
    const int nb0   = split * CHUNKS * BN;

    if (wid >= 4) {
        // ================= E-group: GEMM1 + epilogue =================
        const int et = tid - 128;
        const int RM = (wid - 4) * 32;

        // group 0: X tile + x2
        #pragma unroll 1
        for (int it = 0; it < 16; ++it) {
            int idx = it * 128 + et;
            int row = idx >> 4, qc = idx & 15;
            cp16(sb + (XH_O + row * 68 + qc * 4) * 4,
                 xh_g + (size_t)(db + row) * KD + qc * 8);
        }
        if (et < 32) cp16(sb + (X2_O + et * 4) * 4, x2_g + db + et * 4);
        cpcommit();

        // group 1: C chunk 0 + c2
        #pragma unroll 1
        for (int it = 0; it < 16; ++it) {
            int idx = it * 128 + et;
            int row = idx >> 4, qc = idx & 15;
            cp16(sb + (CH_O + row * 68 + qc * 4) * 4,
                 ch_g + (size_t)(nb0 + row) * KD + qc * 8);
        }
        if (et < 32) cp16(sb + (C2_O + et * 4) * 4, c2_g + nb0 + et * 4);
        cpcommit();

        #pragma unroll 1
        for (int c = 0; c < CHUNKS; ++c) {
            const int par = c & 1;

            if (c + 1 < CHUNKS) {
                const int buf = (c + 1) & 1;
                const int nbn = nb0 + (c + 1) * BN;
                #pragma unroll 1
                for (int it = 0; it < 16; ++it) {
                    int idx = it * 128 + et;
                    int row = idx >> 4, qc = idx & 15;
                    cp16(sb + (CH_O + buf * CH_BUF + row * 68 + qc * 4) * 4,
                         ch_g + (size_t)(nbn + row) * KD + qc * 8);
                }
                if (et < 32)
                    cp16(sb + (C2_O + buf * 128 + et * 4) * 4, c2_g + nbn + et * 4);
                cpcommit();
                cpwait<1>();
            } else {
                cpwait<0>();
            }
            barsync(2, 128);   // E-group: chunk c smem visible to all E warps

            const uint32_t* __restrict__ chp = su + CH_O + par * CH_BUF;
            uint32_t* __restrict__ php = su + PH_O + par * PH_BUF;

            #pragma unroll 1
            for (int h = 0; h < 2; ++h) {
                // ---- GEMM1 half: S[32 x 64] over k=128 ----
                float S[2][8][4];
                #pragma unroll
                for (int mt = 0; mt < 2; ++mt)
                    #pragma unroll
                    for (int nt = 0; nt < 8; ++nt)
                        #pragma unroll
                        for (int r = 0; r < 4; ++r) S[mt][nt][r] = 0.f;

                #pragma unroll
                for (int kw = 0; kw < 64; kw += 8) {
                    uint32_t a[2][4], b[8][2];
                    #pragma unroll
                    for (int mt = 0; mt < 2; ++mt) {
                        int r = RM + mt * 16 + gid;
                        a[mt][0] = su[XH_O + r * 68 + kw + ctg];
                        a[mt][1] = su[XH_O + (r + 8) * 68 + kw + ctg];
                        a[mt][2] = su[XH_O + r * 68 + kw + ctg + 4];
                        a[mt][3] = su[XH_O + (r + 8) * 68 + kw + ctg + 4];
                    }
                    #pragma unroll
                    for (int nt = 0; nt < 8; ++nt) {
                        int n = h * 64 + nt * 8 + gid;
                        b[nt][0] = chp[n * 68 + kw + ctg];
                        b[nt][1] = chp[n * 68 + kw + ctg + 4];
                    }
                    #pragma unroll
                    for (int mt = 0; mt < 2; ++mt)
                        #pragma unroll
                        for (int nt = 0; nt < 8; ++nt)
                            mma_f16(S[mt][nt], a[mt], b[nt]);
                }

                // ---- epilogue half: phi -> PH[par] ----
                #pragma unroll
                for (int mt = 0; mt < 2; ++mt) {
                    int rA = RM + mt * 16 + gid, rB = rA + 8;
                    float xA = smf[X2_O + rA], xB = smf[X2_O + rB];
                    #pragma unroll
                    for (int nt = 0; nt < 8; ++nt) {
                        int c0 = h * 64 + nt * 8 + 2 * ctg;
                        float cc0 = smf[C2_O + par * 128 + c0];
                        float cc1 = smf[C2_O + par * 128 + c0 + 1];
                        float p0 = fsqrt_ap(1.f + fmaxf(fmaf(-2.f, S[mt][nt][0], xA + cc0), 0.f));
                        float p1 = fsqrt_ap(1.f + fmaxf(fmaf(-2.f, S[mt][nt][1], xA + cc1), 0.f));
                        float p2 = fsqrt_ap(1.f + fmaxf(fmaf(-2.f, S[mt][nt][2], xB + cc0), 0.f));
                        float p3 = fsqrt_ap(1.f + fmaxf(fmaf(-2.f, S[mt][nt][3], xB + cc1), 0.f));
                        __half2 hA = __floats2half2_rn(p0, p1);
                        __half2 hB = __floats2half2_rn(p2, p3);
                        php[rA * 68 + (c0 >> 1)] = *(uint32_t*)&hA;
                        php[rB * 68 + (c0 >> 1)] = *(uint32_t*)&hB;
                    }
                }
            }
            barsync(1, THREADS);   // R1(c): phi(c) published to G
        }
    } else {
        // ================= G-group: GEMM2 =================
        const int RM = wid * 32;

        // prologue: W chunks 0 and 1
        #pragma unroll 1
        for (int pre = 0; pre < 2; ++pre) {
            const int nbn = nb0 + pre * BN;
            #pragma unroll 1
            for (int it = 0; it < 8; ++it) {
                int idx = it * 128 + tid;
                int l = idx >> 4, qc = idx & 15;
                cp16(sb + (WS_O + pre * WS_BUF + l * 68 + qc * 4) * 4,
                     wt_g + (size_t)l * N_TOT + nbn + qc * 8);
            }
            cpcommit();
        }

        float O[2][8][4];
        #pragma unroll
        for (int mt = 0; mt < 2; ++mt)
            #pragma unroll
            for (int nt = 0; nt < 8; ++nt)
                #pragma unroll
                for (int r = 0; r < 4; ++r) O[mt][nt][r] = 0.f;

        #pragma unroll 1
        for (int c = 0; c < CHUNKS; ++c) {
            const int par = c & 1;

            if (c + 1 < CHUNKS) cpwait<1>(); else cpwait<0>();
            barsync(1, THREADS);   // R1(c): phi(c) ready, W(c) writes drained

            const uint32_t* __restrict__ php = su + PH_O + par * PH_BUF;
            const uint32_t* __restrict__ wsp = su + WS_O + par * WS_BUF;

            #pragma unroll
            for (int kw = 0; kw < 64; kw += 8) {
                uint32_t ah[2][4], bw[8][2];
                #pragma unroll
                for (int mt = 0; mt < 2; ++mt) {
                    int r = RM + mt * 16 + gid;
                    ah[mt][0] = php[r * 68 + kw + ctg];
                    ah[mt][1] = php[(r + 8) * 68 + kw + ctg];
                    ah[mt][2] = php[r * 68 + kw + ctg + 4];
                    ah[mt][3] = php[(r + 8) * 68 + kw + ctg + 4];
                }
                #pragma unroll
                for (int nt = 0; nt < 8; ++nt) {
                    int l = nt * 8 + gid;
                    bw[nt][0] = wsp[l * 68 + kw + ctg];
                    bw[nt][1] = wsp[l * 68 + kw + ctg + 4];
                }
                #pragma unroll
                for (int mt = 0; mt < 2; ++mt)
                    #pragma unroll
                    for (int nt = 0; nt < 8; ++nt)
                        mma_f16(O[mt][nt], ah[mt], bw[nt]);
            }

            barsync(3, 128);       // G-group: all G warps done reading W(c)/phi(c)

            if (c + 2 < CHUNKS) {  // W(c+2) into buffer parity (c+2)&1 == par
                const int nbn = nb0 + (c + 2) * BN;
                #pragma unroll 1
                for (int it = 0; it < 8; ++it) {
                    int idx = it * 128 + tid;
                    int l = idx >> 4, qc = idx & 15;
                    cp16(sb + (WS_O + par * WS_BUF + l * 68 + qc * 4) * 4,
                         wt_g + (size_t)l * N_TOT + nbn + qc * 8);
                }
                cpcommit();
            }
        }

        // ---- merge N-splits ----
        #pragma unroll
        for (int mt = 0; mt < 2; ++mt) {
            int rA = db + RM + mt * 16 + gid;
            #pragma unroll
            for (int nt = 0; nt < 8; ++nt) {
                int c0 = nt * 8 + 2 * ctg;
                atomicAdd(&out[(size_t)rA * LD + c0],           O[mt][nt][0]);
                atomicAdd(&out[(size_t)rA * LD + c0 + 1],       O[mt][nt][1]);
                atomicAdd(&out[(size_t)(rA + 8) * LD + c0],     O[mt][nt][2]);
                atomicAdd(&out[(size_t)(rA + 8) * LD + c0 + 1], O[mt][nt][3]);
            }
        }
    }
}

// ---------------------------------------------------------------------------
extern "C" void kernel_launch(void* const* d_in, const int* in_sizes, int n_in,
                              void* d_out, int out_size) {
    const float* xs     = (const float*)d_in[0];
    const float* centre = (const float*)d_in[1];
    const float* weight = (const float*)d_in[2];
    float* out = (float*)d_out;

    cudaFuncSetAttribute(rbfn_main_kernel,
                         cudaFuncAttributeMaxDynamicSharedMemorySize, SMEM_BYTES);

    cudaMemsetAsync(d_out, 0, (size_t)out_size * sizeof(float));
    prologue_kernel<<<2048 + 128, THREADS>>>(xs, centre, weight);
    rbfn_main_kernel<<<64 * NSPLIT, THREADS, SMEM_BYTES>>>(out);
}